// round 6
// baseline (speedup 1.0000x reference)
#include <cuda_runtime.h>

// FDTD wave cell, fused pointwise + 5-point Laplacian.
// Rolling vertical register window: block = full row (256 thr x float4) x 8 rows.
// Each h1 row is loaded ONCE (prev/cur/next carried in registers) -> L2/LTS
// traffic for h1 drops from 3x to 1.25x. h1-copy output stored from registers.
// Shapes: h1,h2,c_linear,rho: [8,1024,1024] f32; b_geom: [1024,1024] f32.
// Output: concat(y, h1) -> 2*8*1024*1024 f32.
// Constants: DT=0.5 -> dt^-2=4, 2/dt^2=8, dt^-1=2 ; H=1 ; b0=1 ; uth=1 ; c_nl=0.01

#define NX 1024
#define NY 1024
#define NB 8
#define ROWS 8                 // rows per block
#define PLANE (NY * NX)        // 1M elements per batch image

__device__ __forceinline__ float cell(float hh, float hhm1, float hhp1,
                                      float u, float d, float bgv, float rhv,
                                      float clv, float c2v)
{
    const float hh2 = hh * hh;
    const float bv  = bgv + rhv * __frcp_rn(1.0f + hh2);       // saturable damping
    const float cv  = clv + 0.01f * rhv * hh2;                 // nonlinear speed
    const float lap = u + d + hhm1 + hhp1 - 4.0f * hh;         // 5-pt laplacian
    const float inv = __frcp_rn(4.0f + 2.0f * bv);             // 1/(dt^-2 + b dt^-1)
    return inv * (8.0f * hh - (4.0f - 2.0f * bv) * c2v + cv * cv * lap);
}

__global__ __launch_bounds__(256)
void wavecell_kernel(const float* __restrict__ h1,
                     const float* __restrict__ h2,
                     const float* __restrict__ c_linear,
                     const float* __restrict__ rho,
                     const float* __restrict__ b_geom,
                     float* __restrict__ out)
{
    // bid: batch fastest -> blocks on the same rows across batch are adjacent
    // (b_geom rows stay L2-hot); row-group slowest.
    const int bid = blockIdx.x;
    const int b   = bid & (NB - 1);          // 0..7
    const int y0  = (bid >> 3) * ROWS;       // 0,8,...,1016
    const int x0  = threadIdx.x << 2;        // 0..1020 step 4

    const long rowbase = (long)b * PLANE + (long)y0 * NX + x0;
    const long gbase   = (long)y0 * NX + x0;

    const float4 zero = make_float4(0.f, 0.f, 0.f, 0.f);

    // Prime the rolling window
    float4 prev = (y0 > 0) ? *(const float4*)(h1 + rowbase - NX) : zero;
    float4 cur  = *(const float4*)(h1 + rowbase);

#pragma unroll 4
    for (int r = 0; r < ROWS; ++r) {
        const long base = rowbase + (long)r * NX;
        const int  y    = y0 + r;

        // Next h1 row (zero padding at bottom edge)
        float4 next = (y + 1 < NY) ? *(const float4*)(h1 + base + NX) : zero;

        // Use-once operands: streaming loads (evict-first)
        const float4 v2 = __ldcs((const float4*)(h2 + base));
        const float4 vc = __ldcs((const float4*)(c_linear + base));
        const float4 vr = __ldcs((const float4*)(rho + base));
        // b_geom: reused 8x across batch -> default caching
        const float4 vb = *(const float4*)(b_geom + gbase + (long)r * NX);

        // Horizontal edge neighbors of cur row (L1 hits; zero at x boundaries)
        const float left  = (x0 > 0)      ? h1[base - 1] : 0.f;
        const float right = (x0 + 4 < NX) ? h1[base + 4] : 0.f;

        float4 vy;
        vy.x = cell(cur.x, left,  cur.y, prev.x, next.x, vb.x, vr.x, vc.x, v2.x);
        vy.y = cell(cur.y, cur.x, cur.z, prev.y, next.y, vb.y, vr.y, vc.y, v2.y);
        vy.z = cell(cur.z, cur.y, cur.w, prev.z, next.z, vb.z, vr.z, vc.z, v2.z);
        vy.w = cell(cur.w, cur.z, right, prev.w, next.w, vb.w, vr.w, vc.w, v2.w);

        // Streaming stores; h1 copy comes straight from registers (no re-read)
        __stcs((float4*)(out + base), vy);
        __stcs((float4*)(out + (long)NB * PLANE + base), cur);

        prev = cur;
        cur  = next;
    }
}

extern "C" void kernel_launch(void* const* d_in, const int* in_sizes, int n_in,
                              void* d_out, int out_size)
{
    const float* h1       = (const float*)d_in[0];
    const float* h2       = (const float*)d_in[1];
    const float* c_linear = (const float*)d_in[2];
    const float* rho      = (const float*)d_in[3];
    const float* b_geom   = (const float*)d_in[4];
    float* out            = (float*)d_out;

    const int grid = NB * (NY / ROWS);       // 8 * 128 = 1024 blocks
    wavecell_kernel<<<grid, 256>>>(h1, h2, c_linear, rho, b_geom, out);
}

// round 7
// speedup vs baseline: 1.0009x; 1.0009x over previous
#include <cuda_runtime.h>

// FDTD wave cell, fused pointwise + 5-point Laplacian. float4 per thread.
// R3 structure; loads use DEFAULT caching (inputs are re-read every graph
// replay -> keep them L2-resident), stores use __stcs (evict-first) so the
// 64MB of write-once output doesn't evict the input working set from L2.
// Shapes: h1,h2,c_linear,rho: [8,1024,1024] f32; b_geom: [1024,1024] f32.
// Output: concat(y, h1) -> 2*8*1024*1024 f32.
// Constants: DT=0.5 -> dt^-2=4, 2/dt^2=8, dt^-1=2 ; H=1 ; b0=1 ; uth=1 ; c_nl=0.01

#define NX 1024
#define NY 1024
#define NB 8
#define NX4 (NX / 4)          // 256 float4 chunks per row
#define PLANE (NY * NX)       // 1M elements per batch image

__device__ __forceinline__ float cell(float hh, float hhm1, float hhp1,
                                      float u, float d, float bgv, float rhv,
                                      float clv, float c2v)
{
    const float hh2 = hh * hh;
    const float bv  = bgv + rhv * __frcp_rn(1.0f + hh2);       // saturable damping
    const float cv  = clv + 0.01f * rhv * hh2;                 // nonlinear speed
    const float lap = u + d + hhm1 + hhp1 - 4.0f * hh;         // 5-pt laplacian
    const float inv = __frcp_rn(4.0f + 2.0f * bv);             // 1/(dt^-2 + b dt^-1)
    return inv * (8.0f * hh - (4.0f - 2.0f * bv) * c2v + cv * cv * lap);
}

__global__ __launch_bounds__(256)
void wavecell_kernel(const float* __restrict__ h1,
                     const float* __restrict__ h2,
                     const float* __restrict__ c_linear,
                     const float* __restrict__ rho,
                     const float* __restrict__ b_geom,
                     float* __restrict__ out)
{
    // Mapping: x4 fastest, batch middle, y slowest (adjacent blocks share rows
    // across batch -> b_geom + vertical-neighbor rows stay L2-resident).
    const int t   = blockIdx.x * blockDim.x + threadIdx.x;
    const int x4  = t & (NX4 - 1);          // 0..255
    const int b   = (t >> 8) & (NB - 1);    // 0..7
    const int y   = t >> 11;                // 0..1023

    const int x0    = x4 * 4;
    const long base = (long)b * PLANE + (long)y * NX + x0;

    // All inputs: default caching (re-read every replay -> want L2 residency)
    const float4 v1 = *(const float4*)(h1 + base);

    // Vertical neighbors (zero padding at y boundaries)
    float4 up   = make_float4(0.f, 0.f, 0.f, 0.f);
    float4 down = make_float4(0.f, 0.f, 0.f, 0.f);
    if (y > 0)      up   = *(const float4*)(h1 + base - NX);
    if (y < NY - 1) down = *(const float4*)(h1 + base + NX);

    const float4 v2 = *(const float4*)(h2 + base);
    const float4 vc = *(const float4*)(c_linear + base);
    const float4 vr = *(const float4*)(rho + base);
    const float4 vb = *(const float4*)(b_geom + (long)y * NX + x0);

    // Horizontal edge neighbors (L1 hits; zero at x boundaries)
    const float left  = (x0 > 0)      ? h1[base - 1] : 0.f;
    const float right = (x0 + 4 < NX) ? h1[base + 4] : 0.f;

    float4 vy;
    vy.x = cell(v1.x, left,  v1.y, up.x, down.x, vb.x, vr.x, vc.x, v2.x);
    vy.y = cell(v1.y, v1.x, v1.z, up.y, down.y, vb.y, vr.y, vc.y, v2.y);
    vy.z = cell(v1.z, v1.y, v1.w, up.z, down.z, vb.z, vr.z, vc.z, v2.z);
    vy.w = cell(v1.w, v1.z, right, up.w, down.w, vb.w, vr.w, vc.w, v2.w);

    // Streaming stores (write-once, never re-read -> keep them out of L2)
    __stcs((float4*)(out + base), vy);
    __stcs((float4*)(out + (long)NB * PLANE + base), v1);
}

extern "C" void kernel_launch(void* const* d_in, const int* in_sizes, int n_in,
                              void* d_out, int out_size)
{
    const float* h1       = (const float*)d_in[0];
    const float* h2       = (const float*)d_in[1];
    const float* c_linear = (const float*)d_in[2];
    const float* rho      = (const float*)d_in[3];
    const float* b_geom   = (const float*)d_in[4];
    float* out            = (float*)d_out;

    const int total_chunks = NB * NY * NX4;   // 2,097,152 threads
    const int block = 256;
    const int grid  = total_chunks / block;   // 8192 blocks
    wavecell_kernel<<<grid, block>>>(h1, h2, c_linear, rho, b_geom, out);
}

// round 8
// speedup vs baseline: 1.0202x; 1.0193x over previous
#include <cuda_runtime.h>

// FDTD wave cell. SMEM-tiled stencil: block = 512x8 tile, h1 staged through
// shared memory (halo 1.25x) so vertical/horizontal neighbors stop transiting
// L2 three times. Cache policy from R3: __ldcs on use-once streams, __stcs on
// write-once outputs.
// Shapes: h1,h2,c_linear,rho: [8,1024,1024] f32; b_geom: [1024,1024] f32.
// Output: concat(y, h1) -> 2*8*1024*1024 f32.
// Constants: DT=0.5 -> dt^-2=4, 2/dt^2=8, dt^-1=2 ; H=1 ; b0=1 ; uth=1 ; c_nl=0.01

#define NX 1024
#define NY 1024
#define NB 8
#define TW 512                 // tile width  (floats)
#define TH 8                   // tile height (rows)
#define TW4 (TW / 4)           // 128 float4 per tile row
#define PLANE (NY * NX)

__device__ __forceinline__ float cell(float hh, float hhm1, float hhp1,
                                      float u, float d, float bgv, float rhv,
                                      float clv, float c2v)
{
    const float hh2 = hh * hh;
    const float bv  = bgv + rhv * __frcp_rn(1.0f + hh2);       // saturable damping
    const float cv  = clv + 0.01f * rhv * hh2;                 // nonlinear speed
    const float lap = u + d + hhm1 + hhp1 - 4.0f * hh;         // 5-pt laplacian
    const float inv = __frcp_rn(4.0f + 2.0f * bv);             // 1/(dt^-2 + b dt^-1)
    return inv * (8.0f * hh - (4.0f - 2.0f * bv) * c2v + cv * cv * lap);
}

__global__ __launch_bounds__(256)
void wavecell_kernel(const float* __restrict__ h1,
                     const float* __restrict__ h2,
                     const float* __restrict__ c_linear,
                     const float* __restrict__ rho,
                     const float* __restrict__ b_geom,
                     float* __restrict__ out)
{
    __shared__ float s[(TH + 2) * TW];      // 10 x 512 floats = 20 KB

    // bid: batch fastest (b_geom rows shared across batch stay L2-hot),
    // then x-tile, then y-tile.
    const int bid  = blockIdx.x;
    const int b    = bid & (NB - 1);                 // 0..7
    const int tile = bid >> 3;
    const int tx   = tile & 1;                       // 0..1
    const int ty   = tile >> 1;                      // 0..127
    const int tid  = threadIdx.x;

    const int xb = tx * TW;                          // tile x origin
    const int yb = ty * TH;                          // tile y origin
    const long tbase = (long)b * PLANE + (long)yb * NX + xb;   // tile row0 origin

    // ---- Stage h1 tile + vertical halo into SMEM (rows yb-1 .. yb+TH) ----
#pragma unroll
    for (int i = 0; i < 5; ++i) {                    // 5 * 256 = 1280 float4
        const int idx  = i * 256 + tid;
        const int row  = idx >> 7;                   // 0..9
        const int col4 = idx & 127;                  // 0..127
        const int gy   = yb + row - 1;
        float4 v = make_float4(0.f, 0.f, 0.f, 0.f);
        if (gy >= 0 && gy < NY)
            v = *(const float4*)(h1 + (long)b * PLANE + (long)gy * NX + xb + col4 * 4);
        *(float4*)(s + row * TW + col4 * 4) = v;
    }
    __syncthreads();

    // ---- Compute: each thread does 4 rows at one col4 ----
    const int col4 = tid & 127;                      // 0..127
    const int r0   = (tid >> 7) * 4;                 // 0 or 4
    const int c0   = col4 * 4;

#pragma unroll
    for (int rr = 0; rr < 4; ++rr) {
        const int r     = r0 + rr;                   // 0..7 within tile
        const int srow  = (r + 1) * TW;              // SMEM row of this cell row
        const long base = tbase + (long)r * NX + c0;

        const float4 cur  = *(const float4*)(s + srow + c0);
        const float4 up   = *(const float4*)(s + srow - TW + c0);
        const float4 down = *(const float4*)(s + srow + TW + c0);

        // Horizontal neighbors: SMEM within tile, global scalar at tile edge
        float left, right;
        if (c0 > 0)            left = s[srow + c0 - 1];
        else if (xb > 0)       left = h1[base - 1];
        else                   left = 0.f;
        if (c0 + 4 < TW)       right = s[srow + c0 + 4];
        else if (xb + TW < NX) right = h1[base + 4];
        else                   right = 0.f;

        // Use-once streams: evict-first
        const float4 v2 = __ldcs((const float4*)(h2 + base));
        const float4 vc = __ldcs((const float4*)(c_linear + base));
        const float4 vr = __ldcs((const float4*)(rho + base));
        // b_geom: reused 8x across batch
        const float4 vb = *(const float4*)(b_geom + (long)(yb + r) * NX + xb + c0);

        float4 vy;
        vy.x = cell(cur.x, left,  cur.y, up.x, down.x, vb.x, vr.x, vc.x, v2.x);
        vy.y = cell(cur.y, cur.x, cur.z, up.y, down.y, vb.y, vr.y, vc.y, v2.y);
        vy.z = cell(cur.z, cur.y, cur.w, up.z, down.z, vb.z, vr.z, vc.z, v2.z);
        vy.w = cell(cur.w, cur.z, right, up.w, down.w, vb.w, vr.w, vc.w, v2.w);

        __stcs((float4*)(out + base), vy);
        __stcs((float4*)(out + (long)NB * PLANE + base), cur);   // h1 copy from SMEM
    }
}

extern "C" void kernel_launch(void* const* d_in, const int* in_sizes, int n_in,
                              void* d_out, int out_size)
{
    const float* h1       = (const float*)d_in[0];
    const float* h2       = (const float*)d_in[1];
    const float* c_linear = (const float*)d_in[2];
    const float* rho      = (const float*)d_in[3];
    const float* b_geom   = (const float*)d_in[4];
    float* out            = (float*)d_out;

    const int grid = NB * (NX / TW) * (NY / TH);     // 8 * 2 * 128 = 2048 blocks
    wavecell_kernel<<<grid, 256>>>(h1, h2, c_linear, rho, b_geom, out);
}